// round 8
// baseline (speedup 1.0000x reference)
#include <cuda_runtime.h>
#include <cuda_bf16.h>
#include <cstdint>
#include <cstdio>

// Problem constants
#define BB   8
#define SS   2048
#define DD   1024
#define KK   256
#define NFFT 2048
#define K2   512

// ---------------- device scratch ----------------
__device__ __align__(256) float2        g_tbl[NFFT];             // cos/sin table
__device__ __align__(256) __nv_bfloat16 g_basis1[K2 * SS];       // [512][2048] rows 0..255 cos, 256..511 -sin
__device__ __align__(256) __nv_bfloat16 g_basis2[SS * K2];       // [2048][512] irfft basis (c/N folded)
__device__ __align__(256) __nv_bfloat16 g_wt[KK * KK];           // WT[j][k] = W[k][j]
__device__ __align__(256) float         g_cwr[KK * DD];          // mag*cos(ph)
__device__ __align__(256) float         g_cwi[KK * DD];          // mag*sin(ph)
__device__ __align__(256) __nv_bfloat16 g_xbf[BB * SS * DD];     // bf16(x)
__device__ __align__(256) float         g_X[BB * K2 * DD];       // Xr rows 0..255, Xi rows 256..511
__device__ __align__(256) __nv_bfloat16 g_xwr[BB * KK * DD];     // Re(x_weighted)
__device__ __align__(256) float         g_dpart[BB * KK * DD];   // xwr - Xr
__device__ __align__(256) __nv_bfloat16 g_delta[BB * K2 * DD];   // [deltar; deltai]

// ---------------- helpers ----------------
__device__ __forceinline__ int freq_of(int k) {
    if (k == 255) return 512;
    return (int)((double)k * (512.0 / 255.0));
}
__device__ __forceinline__ uint32_t smem_u32(const void* p) {
    return (uint32_t)__cvta_generic_to_shared(p);
}
__device__ __forceinline__ void cp_async16(void* smem_dst, const void* gmem_src) {
    asm volatile("cp.async.cg.shared.global [%0], [%1], 16;\n"
                 :: "r"(smem_u32(smem_dst)), "l"(gmem_src));
}
__device__ __forceinline__ void cp_commit() {
    asm volatile("cp.async.commit_group;\n");
}
template <int N>
__device__ __forceinline__ void cp_wait() {
    asm volatile("cp.async.wait_group %0;\n" :: "n"(N));
}

// ---------------- precompute ----------------
__global__ void k_tbl() {
    int m = blockIdx.x * blockDim.x + threadIdx.x;
    float ang = (float)m * (6.28318530717958647692f / (float)NFFT);
    float sv, cv;
    sincosf(ang, &sv, &cv);
    g_tbl[m] = make_float2(cv, sv);
}

// merged: basis1, basis2, wt, cw
#define N_B1 (K2 * SS)
#define N_B2 (N_B1 + SS * K2)
#define N_WT (N_B2 + KK * KK)
#define N_CW (N_WT + KK * DD)
__global__ void k_pre(const float* __restrict__ W,
                      const float* __restrict__ mag, const float* __restrict__ ph) {
    int idx = blockIdx.x * blockDim.x + threadIdx.x;
    if (idx < N_B1) {
        int row = idx >> 11;          // 0..511
        int s   = idx & 2047;
        int f   = freq_of(row & 255);
        float2 t = g_tbl[(f * s) & (NFFT - 1)];
        g_basis1[idx] = __float2bfloat16((row < KK) ? t.x : -t.y);
    } else if (idx < N_B2) {
        int i = idx - N_B1;
        int s   = i >> 9;             // 0..2047
        int col = i & 511;            // 0..511
        int f   = freq_of(col & 255);
        float2 t = g_tbl[(f * s) & (NFFT - 1)];
        float scale = ((f == 0) ? 1.0f : 2.0f) * (1.0f / (float)NFFT);
        g_basis2[i] = __float2bfloat16((col < KK) ? (scale * t.x) : (-scale * t.y));
    } else if (idx < N_WT) {
        int i = idx - N_B2;
        int j = i >> 8, k = i & 255;
        g_wt[i] = __float2bfloat16(W[k * KK + j]);
    } else if (idx < N_CW) {
        int i = idx - N_WT;
        float sp, cp;
        sincosf(ph[i], &sp, &cp);
        float m = mag[i];
        g_cwr[i] = m * cp;
        g_cwi[i] = m * sp;
    }
}

__global__ void k_convert(const float* __restrict__ x) {
    int i = blockIdx.x * blockDim.x + threadIdx.x;
    if (i >= (BB * SS * DD) / 4) return;
    float4 v = ((const float4*)x)[i];
    __nv_bfloat162* o = (__nv_bfloat162*)g_xbf;
    o[2 * i]     = __floats2bfloat162_rn(v.x, v.y);
    o[2 * i + 1] = __floats2bfloat162_rn(v.z, v.w);
}

// ---------------- elementwise complex weighting (table-driven) ----------------
__global__ void k_elem() {
    int idx = blockIdx.x * blockDim.x + threadIdx.x;
    if (idx >= BB * KK * DD) return;
    int b = idx >> 18;
    int r = idx & 262143;   // k*1024 + d
    size_t xb = (size_t)b * (K2 * DD);
    float Xr = g_X[xb + r];
    float Xi = g_X[xb + (KK * DD) + r];
    float cr = g_cwr[r];
    float ci = g_cwi[r];
    float xwr = Xr * cr - Xi * ci;
    float xwi = Xr * ci + Xi * cr;
    g_xwr[idx]   = __float2bfloat16(xwr);
    g_dpart[idx] = xwr - Xr;
    g_delta[xb + (KK * DD) + r] = __float2bfloat16(xwi - Xi);
}

// ================= big-tile GEMM engine: 128x256x32, 8 warps @ 64x64 =================
// C[m][n] = sum_k A[m][k] * B[k][n]
// MODE 0: C = acc (fp32)          MODE 2: C = acc + 2*aux (fp32)
#define TBM 128
#define TBN 256
#define TBK 32
#define TNST 3
#define TA_BYTES (TBM * 40 * 2)        // 10240
#define TB_BYTES (TBK * 264 * 2)       // 16896
#define TSTAGE (TA_BYTES + TB_BYTES)   // 27136
#define TSMEM (TNST * TSTAGE)          // 81408

template <int MODE>
__global__ __launch_bounds__(256, 1) void gemm_big(
    const __nv_bfloat16* __restrict__ A, int ldA,
    const __nv_bfloat16* __restrict__ Bm, size_t sB, int ldB,
    float* __restrict__ C, size_t sC, int ldC,
    const float* __restrict__ aux, size_t sAux,
    int Kdim)
{
    extern __shared__ __align__(16) char dsm[];

    int bz = blockIdx.z;
    int bm = blockIdx.y * TBM;
    int bn = blockIdx.x * TBN;
    const __nv_bfloat16* Ab = A;
    const __nv_bfloat16* Bb = Bm + sB * bz;

    int tid = threadIdx.x, lane = tid & 31, warp = tid >> 5;
    int wm = (warp & 1) * 64;    // 2 warps along M
    int wn = (warp >> 1) * 64;   // 4 warps along N

    float acc[4][8][4];
#pragma unroll
    for (int i = 0; i < 4; i++)
#pragma unroll
        for (int j = 0; j < 8; j++)
#pragma unroll
            for (int c = 0; c < 4; c++) acc[i][j][c] = 0.f;

    auto st_base = [&](int st) -> char* { return dsm + st * TSTAGE; };

    // per-thread load coords
    int a_r = tid >> 2;              // 0..63 (+64)
    int a_c = (tid & 3) << 3;
    int b_r = tid >> 5;              // 0..7 (+8,+16,+24)
    int b_c = (tid & 31) << 3;

    auto load_stage = [&](int s) {
        char* ap = st_base(s % TNST);
        char* bp = ap + TA_BYTES;
        int k0 = s * TBK;
        cp_async16(ap + (a_r * 40 + a_c) * 2,        Ab + (size_t)(bm + a_r) * ldA + k0 + a_c);
        cp_async16(ap + ((a_r + 64) * 40 + a_c) * 2, Ab + (size_t)(bm + a_r + 64) * ldA + k0 + a_c);
#pragma unroll
        for (int j = 0; j < 4; j++)
            cp_async16(bp + ((b_r + 8 * j) * 264 + b_c) * 2,
                       Bb + (size_t)(k0 + b_r + 8 * j) * ldB + bn + b_c);
        cp_commit();
    };

    load_stage(0);
    load_stage(1);

    int nt = Kdim / TBK;
    for (int kt = 0; kt < nt; kt++) {
        cp_wait<1>();
        __syncthreads();
        if (kt + 2 < nt) load_stage(kt + 2);
        else             cp_commit();

        char* ap = st_base(kt % TNST);
        char* bp = ap + TA_BYTES;

#pragma unroll
        for (int kk = 0; kk < TBK; kk += 16) {
            uint32_t af[4][4], bq[4][4];
            int ar = wm + (lane & 15);
            int ac = kk + ((lane >> 4) << 3);
#pragma unroll
            for (int mi = 0; mi < 4; mi++) {
                uint32_t ad = smem_u32(ap + ((ar + mi * 16) * 40 + ac) * 2);
                asm volatile("ldmatrix.sync.aligned.m8n8.x4.shared.b16 {%0,%1,%2,%3}, [%4];"
                             : "=r"(af[mi][0]), "=r"(af[mi][1]), "=r"(af[mi][2]), "=r"(af[mi][3])
                             : "r"(ad));
            }
            int brr = kk + (lane & 15);
            int bcc = (lane >> 4) << 3;
#pragma unroll
            for (int nj = 0; nj < 4; nj++) {
                uint32_t bd = smem_u32(bp + (brr * 264 + wn + nj * 16 + bcc) * 2);
                asm volatile("ldmatrix.sync.aligned.m8n8.x4.trans.shared.b16 {%0,%1,%2,%3}, [%4];"
                             : "=r"(bq[nj][0]), "=r"(bq[nj][1]), "=r"(bq[nj][2]), "=r"(bq[nj][3])
                             : "r"(bd));
            }
#pragma unroll
            for (int mi = 0; mi < 4; mi++)
#pragma unroll
                for (int ni = 0; ni < 8; ni++) {
                    float* d = acc[mi][ni];
                    uint32_t b0 = bq[ni >> 1][(ni & 1) * 2];
                    uint32_t b1 = bq[ni >> 1][(ni & 1) * 2 + 1];
                    asm volatile(
                        "mma.sync.aligned.m16n8k16.row.col.f32.bf16.bf16.f32 "
                        "{%0,%1,%2,%3}, {%4,%5,%6,%7}, {%8,%9}, {%0,%1,%2,%3};"
                        : "+f"(d[0]), "+f"(d[1]), "+f"(d[2]), "+f"(d[3])
                        : "r"(af[mi][0]), "r"(af[mi][1]), "r"(af[mi][2]), "r"(af[mi][3]),
                          "r"(b0), "r"(b1));
                }
        }
    }

    int g = lane >> 2, t2 = (lane & 3) << 1;
    float* Cb = C + sC * bz;
    const float* axb = (MODE == 2) ? (aux + sAux * bz) : nullptr;
#pragma unroll
    for (int mi = 0; mi < 4; mi++) {
#pragma unroll
        for (int ni = 0; ni < 8; ni++) {
            int row0 = bm + wm + mi * 16 + g;
            int col  = bn + wn + ni * 8 + t2;
            float* d = acc[mi][ni];
            if (MODE == 0) {
                *(float2*)&Cb[(size_t)row0 * ldC + col]       = make_float2(d[0], d[1]);
                *(float2*)&Cb[(size_t)(row0 + 8) * ldC + col] = make_float2(d[2], d[3]);
            } else {
                float2 a0 = *(const float2*)&axb[(size_t)row0 * ldC + col];
                float2 a1 = *(const float2*)&axb[(size_t)(row0 + 8) * ldC + col];
                *(float2*)&Cb[(size_t)row0 * ldC + col] =
                    make_float2(d[0] + 2.f * a0.x, d[1] + 2.f * a0.y);
                *(float2*)&Cb[(size_t)(row0 + 8) * ldC + col] =
                    make_float2(d[2] + 2.f * a1.x, d[3] + 2.f * a1.y);
            }
        }
    }
}

// ---------------- interference GEMM (128x128 engine, C = aux + 0.1*acc, bf16) ----
#define BM 128
#define BN 128
#define BKg 32
#define NSTG 4
#define A_BYTES (BM * 40 * 2)
#define B_BYTES (BKg * 136 * 2)
#define GEMM_SMEM (NSTG * (A_BYTES + B_BYTES))

__global__ __launch_bounds__(256, 2) void gemm_mma1(
    const __nv_bfloat16* __restrict__ A, int ldA,
    const __nv_bfloat16* __restrict__ Bm, size_t sB, int ldB,
    __nv_bfloat16* __restrict__ Cv, size_t sC, int ldC,
    const float* __restrict__ aux, size_t sAux,
    int Kdim)
{
    extern __shared__ __align__(16) char dsm[];

    int bz = blockIdx.z;
    int bm = blockIdx.y * BM;
    int bn = blockIdx.x * BN;
    const __nv_bfloat16* Ab = A;
    const __nv_bfloat16* Bb = Bm + sB * bz;

    int tid = threadIdx.x, lane = tid & 31, warp = tid >> 5;
    int wm = (warp & 1) * 64;
    int wn = (warp >> 1) * 32;

    int a_r0 = tid >> 2;
    int a_c  = (tid & 3) << 3;
    int b_r0 = tid >> 4;
    int b_c  = (tid & 15) << 3;

    float acc[4][4][4];
#pragma unroll
    for (int i = 0; i < 4; i++)
#pragma unroll
        for (int j = 0; j < 4; j++)
#pragma unroll
            for (int c = 0; c < 4; c++) acc[i][j][c] = 0.f;

    int nt = Kdim / BKg;

    auto a_base = [&](int st) -> char* { return dsm + st * A_BYTES; };
    auto b_base = [&](int st) -> char* { return dsm + NSTG * A_BYTES + st * B_BYTES; };

    auto load_stage = [&](int s) {
        char* ap = a_base(s & (NSTG - 1));
        char* bp = b_base(s & (NSTG - 1));
        int k0 = s * BKg;
        cp_async16(ap + (a_r0 * 40 + a_c) * 2,        Ab + (size_t)(bm + a_r0) * ldA + k0 + a_c);
        cp_async16(ap + ((a_r0 + 64) * 40 + a_c) * 2, Ab + (size_t)(bm + a_r0 + 64) * ldA + k0 + a_c);
        cp_async16(bp + (b_r0 * 136 + b_c) * 2,        Bb + (size_t)(k0 + b_r0) * ldB + bn + b_c);
        cp_async16(bp + ((b_r0 + 16) * 136 + b_c) * 2, Bb + (size_t)(k0 + b_r0 + 16) * ldB + bn + b_c);
        cp_commit();
    };

#pragma unroll
    for (int i = 0; i < NSTG - 1; i++) load_stage(i);

    for (int kt = 0; kt < nt; kt++) {
        cp_wait<NSTG - 2>();
        __syncthreads();
        if (kt + NSTG - 1 < nt) load_stage(kt + NSTG - 1);
        else                    cp_commit();

        char* ap = a_base(kt & (NSTG - 1));
        char* bp = b_base(kt & (NSTG - 1));

#pragma unroll
        for (int kk = 0; kk < BKg; kk += 16) {
            uint32_t af[4][4], bf[4][2];
            int ar = wm + (lane & 15);
            int ac = kk + ((lane >> 4) << 3);
#pragma unroll
            for (int mi = 0; mi < 4; mi++) {
                uint32_t ad = smem_u32(ap + ((ar + mi * 16) * 40 + ac) * 2);
                asm volatile("ldmatrix.sync.aligned.m8n8.x4.shared.b16 {%0,%1,%2,%3}, [%4];"
                             : "=r"(af[mi][0]), "=r"(af[mi][1]), "=r"(af[mi][2]), "=r"(af[mi][3])
                             : "r"(ad));
            }
            int br = kk + (lane & 15);
#pragma unroll
            for (int ni = 0; ni < 4; ni++) {
                uint32_t bd = smem_u32(bp + (br * 136 + wn + ni * 8) * 2);
                asm volatile("ldmatrix.sync.aligned.m8n8.x2.trans.shared.b16 {%0,%1}, [%2];"
                             : "=r"(bf[ni][0]), "=r"(bf[ni][1]) : "r"(bd));
            }
#pragma unroll
            for (int mi = 0; mi < 4; mi++)
#pragma unroll
                for (int ni = 0; ni < 4; ni++) {
                    float* d = acc[mi][ni];
                    asm volatile(
                        "mma.sync.aligned.m16n8k16.row.col.f32.bf16.bf16.f32 "
                        "{%0,%1,%2,%3}, {%4,%5,%6,%7}, {%8,%9}, {%0,%1,%2,%3};"
                        : "+f"(d[0]), "+f"(d[1]), "+f"(d[2]), "+f"(d[3])
                        : "r"(af[mi][0]), "r"(af[mi][1]), "r"(af[mi][2]), "r"(af[mi][3]),
                          "r"(bf[ni][0]), "r"(bf[ni][1]));
                }
        }
    }

    int g = lane >> 2, t2 = (lane & 3) << 1;
#pragma unroll
    for (int mi = 0; mi < 4; mi++) {
#pragma unroll
        for (int ni = 0; ni < 4; ni++) {
            int row0 = bm + wm + mi * 16 + g;
            int col  = bn + wn + ni * 8 + t2;
            float* d = acc[mi][ni];
            __nv_bfloat16* Cp = Cv + sC * bz;
            const float* ax = aux + sAux * bz;
            float2 a0 = *(const float2*)&ax[(size_t)row0 * ldC + col];
            float2 a1 = *(const float2*)&ax[(size_t)(row0 + 8) * ldC + col];
            *(__nv_bfloat162*)&Cp[(size_t)row0 * ldC + col] =
                __floats2bfloat162_rn(a0.x + 0.1f * d[0], a0.y + 0.1f * d[1]);
            *(__nv_bfloat162*)&Cp[(size_t)(row0 + 8) * ldC + col] =
                __floats2bfloat162_rn(a1.x + 0.1f * d[2], a1.y + 0.1f * d[3]);
        }
    }
}

// ---------------- LayerNorm over D=1024, in place ----------------
__global__ void k_ln(float* __restrict__ y, const float* __restrict__ gamma,
                     const float* __restrict__ beta) {
    int row = blockIdx.x;
    float4* p = (float4*)(y + (size_t)row * DD);
    int t = threadIdx.x;
    float4 v = p[t];
    float s1 = v.x + v.y + v.z + v.w;
    float s2 = v.x * v.x + v.y * v.y + v.z * v.z + v.w * v.w;
#pragma unroll
    for (int o = 16; o > 0; o >>= 1) {
        s1 += __shfl_down_sync(0xffffffffu, s1, o);
        s2 += __shfl_down_sync(0xffffffffu, s2, o);
    }
    __shared__ float r1[8], r2[8];
    int w = t >> 5, l = t & 31;
    if (l == 0) { r1[w] = s1; r2[w] = s2; }
    __syncthreads();
    float mu = 0.f, m2 = 0.f;
#pragma unroll
    for (int i = 0; i < 8; i++) { mu += r1[i]; m2 += r2[i]; }
    mu *= (1.0f / (float)DD);
    float var = m2 * (1.0f / (float)DD) - mu * mu;
    float rs = rsqrtf(var + 1e-5f);
    float4 g = ((const float4*)gamma)[t];
    float4 bb = ((const float4*)beta)[t];
    v.x = (v.x - mu) * rs * g.x + bb.x;
    v.y = (v.y - mu) * rs * g.y + bb.y;
    v.z = (v.z - mu) * rs * g.z + bb.z;
    v.w = (v.w - mu) * rs * g.w + bb.w;
    p[t] = v;
}

// ---------------- launch ----------------
extern "C" void kernel_launch(void* const* d_in, const int* in_sizes, int n_in,
                              void* d_out, int out_size) {
    const float* x     = (const float*)d_in[0];
    const float* mag   = (const float*)d_in[1];
    const float* ph    = (const float*)d_in[2];
    const float* W     = (const float*)d_in[3];
    const float* gamma = (const float*)d_in[4];
    const float* beta  = (const float*)d_in[5];
    float* out = (float*)d_out;

    void *p_b1, *p_b2, *p_wt, *p_xbf, *p_X, *p_xwr, *p_dp, *p_dl;
    cudaGetSymbolAddress(&p_b1, g_basis1);
    cudaGetSymbolAddress(&p_b2, g_basis2);
    cudaGetSymbolAddress(&p_wt, g_wt);
    cudaGetSymbolAddress(&p_xbf, g_xbf);
    cudaGetSymbolAddress(&p_X, g_X);
    cudaGetSymbolAddress(&p_xwr, g_xwr);
    cudaGetSymbolAddress(&p_dp, g_dpart);
    cudaGetSymbolAddress(&p_dl, g_delta);

    cudaFuncSetAttribute(gemm_big<0>, cudaFuncAttributeMaxDynamicSharedMemorySize, TSMEM);
    cudaFuncSetAttribute(gemm_big<2>, cudaFuncAttributeMaxDynamicSharedMemorySize, TSMEM);
    cudaFuncSetAttribute(gemm_mma1, cudaFuncAttributeMaxDynamicSharedMemorySize, GEMM_SMEM);

    // 1. precompute (2 launches) + convert
    k_tbl<<<NFFT / 256, 256>>>();
    k_pre<<<(N_CW + 255) / 256, 256>>>(W, mag, ph);
    k_convert<<<(BB * SS * DD / 4) / 256, 256>>>(x);

    // 2. G1: X[b] (512x1024) = basis1 (512x2048) @ xbf[b] (2048x1024)
    gemm_big<0><<<dim3(DD / TBN, K2 / TBM, BB), 256, TSMEM>>>(
        (const __nv_bfloat16*)p_b1, SS,
        (const __nv_bfloat16*)p_xbf, (size_t)SS * DD, DD,
        (float*)p_X, (size_t)K2 * DD, DD,
        nullptr, 0,
        SS);

    // 3. elementwise complex weighting (table-driven)
    k_elem<<<(BB * KK * DD) / 256, 256>>>();

    // 4. interference: deltar[b] = dpart + 0.1 * (WT @ xwr[b])
    gemm_mma1<<<dim3(DD / BN, KK / BM, BB), 256, GEMM_SMEM>>>(
        (const __nv_bfloat16*)p_wt, KK,
        (const __nv_bfloat16*)p_xwr, (size_t)KK * DD, DD,
        (__nv_bfloat16*)p_dl, (size_t)K2 * DD, DD,
        (const float*)p_dp, (size_t)KK * DD,
        KK);

    // 5. G2: out[b] (2048x1024) = basis2 (2048x512) @ delta[b] (512x1024) + 2*x[b]
    gemm_big<2><<<dim3(DD / TBN, SS / TBM, BB), 256, TSMEM>>>(
        (const __nv_bfloat16*)p_b2, K2,
        (const __nv_bfloat16*)p_dl, (size_t)K2 * DD, DD,
        out, (size_t)SS * DD, DD,
        x, (size_t)SS * DD,
        K2);

    // 6. LayerNorm in place
    k_ln<<<BB * SS, 256>>>(out, gamma, beta);
}

// round 9
// speedup vs baseline: 1.0691x; 1.0691x over previous
#include <cuda_runtime.h>
#include <cuda_bf16.h>
#include <cstdint>
#include <cstdio>

// Problem constants
#define BB   8
#define SS   2048
#define DD   1024
#define KK   256
#define NFFT 2048
#define K2   512
#define SH   1024   // folded length

// ---------------- device scratch ----------------
__device__ __align__(256) float2        g_tbl[NFFT];              // cos/sin table
__device__ __align__(256) __nv_bfloat16 g_basis1f[K2 * SH];       // rows 0..255 cos(f*s), 256..511 -sin(f*s); col = s-1
__device__ __align__(256) __nv_bfloat16 g_basis2f[2 * SH * KK];   // rows 0..1023 (c/N)cos, rows 1024..2047 -(c/N)sin
__device__ __align__(256) __nv_bfloat16 g_wt[KK * KK];            // WT[j][k] = W[k][j]
__device__ __align__(256) float         g_cwr[KK * DD];           // mag*cos(ph)
__device__ __align__(256) float         g_cwi[KK * DD];           // mag*sin(ph)
__device__ __align__(256) __nv_bfloat16 g_xc[BB * SH * DD];       // x_s + x_{2048-s}
__device__ __align__(256) __nv_bfloat16 g_xd[BB * SH * DD];       // x_s - x_{2048-s}
__device__ __align__(256) float         g_X[BB * K2 * DD];        // Xr rows 0..255, Xi rows 256..511
__device__ __align__(256) __nv_bfloat16 g_xwr[BB * KK * DD];      // Re(x_weighted)
__device__ __align__(256) float         g_dpart[BB * KK * DD];    // xwr - Xr
__device__ __align__(256) __nv_bfloat16 g_delta[BB * K2 * DD];    // [deltar; deltai]

// ---------------- helpers ----------------
__device__ __forceinline__ int freq_of(int k) {
    if (k == 255) return 512;
    return (int)((double)k * (512.0 / 255.0));
}
__device__ __forceinline__ uint32_t smem_u32(const void* p) {
    return (uint32_t)__cvta_generic_to_shared(p);
}
__device__ __forceinline__ void cp_async16(void* smem_dst, const void* gmem_src) {
    asm volatile("cp.async.cg.shared.global [%0], [%1], 16;\n"
                 :: "r"(smem_u32(smem_dst)), "l"(gmem_src));
}
__device__ __forceinline__ void cp_commit() {
    asm volatile("cp.async.commit_group;\n");
}
template <int N>
__device__ __forceinline__ void cp_wait() {
    asm volatile("cp.async.wait_group %0;\n" :: "n"(N));
}

// ---------------- precompute ----------------
__global__ void k_tbl() {
    int m = blockIdx.x * blockDim.x + threadIdx.x;
    float ang = (float)m * (6.28318530717958647692f / (float)NFFT);
    float sv, cv;
    sincosf(ang, &sv, &cv);
    g_tbl[m] = make_float2(cv, sv);
}

// merged precompute: basis1f, basis2f, wt, cw
#define N_B1 (K2 * SH)
#define N_B2 (N_B1 + 2 * SH * KK)
#define N_WT (N_B2 + KK * KK)
#define N_CW (N_WT + KK * DD)
__global__ void k_pre(const float* __restrict__ W,
                      const float* __restrict__ mag, const float* __restrict__ ph) {
    int idx = blockIdx.x * blockDim.x + threadIdx.x;
    if (idx < N_B1) {
        int row = idx >> 10;             // 0..511
        int s   = (idx & 1023) + 1;      // 1..1024
        int f   = freq_of(row & 255);
        float2 t = g_tbl[(f * s) & (NFFT - 1)];
        g_basis1f[idx] = __float2bfloat16((row < KK) ? t.x : -t.y);
    } else if (idx < N_B2) {
        int i = idx - N_B1;
        int row = i >> 8;                // 0..2047
        int j   = i & 255;
        int s   = row & 1023;
        int f   = freq_of(j);
        float2 t = g_tbl[(f * s) & (NFFT - 1)];
        float scale = ((f == 0) ? 1.0f : 2.0f) * (1.0f / (float)NFFT);
        g_basis2f[i] = __float2bfloat16((row < SH) ? (scale * t.x) : (-scale * t.y));
    } else if (idx < N_WT) {
        int i = idx - N_B2;
        int j = i >> 8, k = i & 255;
        g_wt[i] = __float2bfloat16(W[k * KK + j]);
    } else if (idx < N_CW) {
        int i = idx - N_WT;
        float sp, cp;
        sincosf(ph[i], &sp, &cp);
        float m = mag[i];
        g_cwr[i] = m * cp;
        g_cwi[i] = m * sp;
    }
}

// ---------------- fold ----------------
__global__ void k_fold(const float* __restrict__ x) {
    int idx = blockIdx.x * blockDim.x + threadIdx.x;
    if (idx >= BB * SH * (DD / 4)) return;
    int b   = idx >> 18;
    int r   = idx & 262143;
    int srow = r >> 8;
    int d4   = (r & 255) << 2;
    int s = srow + 1;
    const float* xb = x + (size_t)b * SS * DD;
    float4 xs = *(const float4*)(xb + (size_t)s * DD + d4);
    float4 c, d;
    if (s == 1024) {
        c = xs;
        d = make_float4(0.f, 0.f, 0.f, 0.f);
    } else {
        float4 xm = *(const float4*)(xb + (size_t)(SS - s) * DD + d4);
        c = make_float4(xs.x + xm.x, xs.y + xm.y, xs.z + xm.z, xs.w + xm.w);
        d = make_float4(xs.x - xm.x, xs.y - xm.y, xs.z - xm.z, xs.w - xm.w);
    }
    size_t o = ((size_t)b * SH + srow) * DD + d4;
    *(__nv_bfloat162*)&g_xc[o]     = __floats2bfloat162_rn(c.x, c.y);
    *(__nv_bfloat162*)&g_xc[o + 2] = __floats2bfloat162_rn(c.z, c.w);
    *(__nv_bfloat162*)&g_xd[o]     = __floats2bfloat162_rn(d.x, d.y);
    *(__nv_bfloat162*)&g_xd[o + 2] = __floats2bfloat162_rn(d.z, d.w);
}

// ---------------- elementwise complex weighting (table-driven, no sincos) ----------------
__global__ void k_elem() {
    int idx = blockIdx.x * blockDim.x + threadIdx.x;
    if (idx >= BB * KK * DD) return;
    int b = idx >> 18;
    int r = idx & 262143;   // k*1024 + d
    size_t xb = (size_t)b * (K2 * DD);
    float Xr = g_X[xb + r];
    float Xi = g_X[xb + (KK * DD) + r];
    float cr = g_cwr[r];
    float ci = g_cwi[r];
    float xwr = Xr * cr - Xi * ci;
    float xwi = Xr * ci + Xi * cr;
    g_xwr[idx]   = __float2bfloat16(xwr);
    g_dpart[idx] = xwr - Xr;
    g_delta[xb + (KK * DD) + r] = __float2bfloat16(xwi - Xi);
}

// ---------------- generic GEMM (G1 folded + interference), 4-stage pipeline ----------------
#define BM 128
#define BN 128
#define BKg 32
#define NSTG 4
#define A_BYTES (BM * 40 * 2)
#define B_BYTES (BKg * 136 * 2)
#define GEMM_SMEM (NSTG * (A_BYTES + B_BYTES))

// MODE 1: bf16 store: aux + 0.1*acc  (interference)
// MODE 3: fp32 store: acc (+ aux_row0[col] if aux && by<bsel)
template <int MODE>
__global__ __launch_bounds__(256, 2) void gemm_mma(
    const __nv_bfloat16* __restrict__ A, int ldA,
    const __nv_bfloat16* __restrict__ B0, const __nv_bfloat16* __restrict__ B1,
    size_t sB, int ldB,
    void* __restrict__ Cv, size_t sC, int ldC,
    const float* __restrict__ aux, size_t sAux,
    int Kdim, int bsel)
{
    extern __shared__ __align__(16) char dsm[];

    int bz = blockIdx.z;
    int bm = blockIdx.y * BM;
    int bn = blockIdx.x * BN;
    const __nv_bfloat16* Ab = A;
    const __nv_bfloat16* Bb = ((int)blockIdx.y < bsel ? B0 : B1) + sB * bz;

    int tid = threadIdx.x, lane = tid & 31, warp = tid >> 5;
    int wm = (warp & 1) * 64;
    int wn = (warp >> 1) * 32;

    int a_r0 = tid >> 2;
    int a_c  = (tid & 3) << 3;
    int b_r0 = tid >> 4;
    int b_c  = (tid & 15) << 3;

    float acc[4][4][4];
#pragma unroll
    for (int i = 0; i < 4; i++)
#pragma unroll
        for (int j = 0; j < 4; j++)
#pragma unroll
            for (int c = 0; c < 4; c++) acc[i][j][c] = 0.f;

    int nt = Kdim / BKg;

    auto a_base = [&](int st) -> char* { return dsm + st * A_BYTES; };
    auto b_base = [&](int st) -> char* { return dsm + NSTG * A_BYTES + st * B_BYTES; };

    auto load_stage = [&](int s) {
        char* ap = a_base(s & (NSTG - 1));
        char* bp = b_base(s & (NSTG - 1));
        int k0 = s * BKg;
        cp_async16(ap + (a_r0 * 40 + a_c) * 2,        Ab + (size_t)(bm + a_r0) * ldA + k0 + a_c);
        cp_async16(ap + ((a_r0 + 64) * 40 + a_c) * 2, Ab + (size_t)(bm + a_r0 + 64) * ldA + k0 + a_c);
        cp_async16(bp + (b_r0 * 136 + b_c) * 2,        Bb + (size_t)(k0 + b_r0) * ldB + bn + b_c);
        cp_async16(bp + ((b_r0 + 16) * 136 + b_c) * 2, Bb + (size_t)(k0 + b_r0 + 16) * ldB + bn + b_c);
        cp_commit();
    };

#pragma unroll
    for (int i = 0; i < NSTG - 1; i++) load_stage(i);

    for (int kt = 0; kt < nt; kt++) {
        cp_wait<NSTG - 2>();
        __syncthreads();
        if (kt + NSTG - 1 < nt) load_stage(kt + NSTG - 1);
        else                    cp_commit();

        char* ap = a_base(kt & (NSTG - 1));
        char* bp = b_base(kt & (NSTG - 1));

#pragma unroll
        for (int kk = 0; kk < BKg; kk += 16) {
            uint32_t af[4][4], bf[4][2];
            int ar = wm + (lane & 15);
            int ac = kk + ((lane >> 4) << 3);
#pragma unroll
            for (int mi = 0; mi < 4; mi++) {
                uint32_t ad = smem_u32(ap + ((ar + mi * 16) * 40 + ac) * 2);
                asm volatile("ldmatrix.sync.aligned.m8n8.x4.shared.b16 {%0,%1,%2,%3}, [%4];"
                             : "=r"(af[mi][0]), "=r"(af[mi][1]), "=r"(af[mi][2]), "=r"(af[mi][3])
                             : "r"(ad));
            }
            int br = kk + (lane & 15);
#pragma unroll
            for (int ni = 0; ni < 4; ni++) {
                uint32_t bd = smem_u32(bp + (br * 136 + wn + ni * 8) * 2);
                asm volatile("ldmatrix.sync.aligned.m8n8.x2.trans.shared.b16 {%0,%1}, [%2];"
                             : "=r"(bf[ni][0]), "=r"(bf[ni][1]) : "r"(bd));
            }
#pragma unroll
            for (int mi = 0; mi < 4; mi++)
#pragma unroll
                for (int ni = 0; ni < 4; ni++) {
                    float* d = acc[mi][ni];
                    asm volatile(
                        "mma.sync.aligned.m16n8k16.row.col.f32.bf16.bf16.f32 "
                        "{%0,%1,%2,%3}, {%4,%5,%6,%7}, {%8,%9}, {%0,%1,%2,%3};"
                        : "+f"(d[0]), "+f"(d[1]), "+f"(d[2]), "+f"(d[3])
                        : "r"(af[mi][0]), "r"(af[mi][1]), "r"(af[mi][2]), "r"(af[mi][3]),
                          "r"(bf[ni][0]), "r"(bf[ni][1]));
                }
        }
    }

    int g = lane >> 2, t2 = (lane & 3) << 1;
    bool addx = (MODE == 3) && (aux != nullptr) && ((int)blockIdx.y < bsel);
#pragma unroll
    for (int mi = 0; mi < 4; mi++) {
#pragma unroll
        for (int ni = 0; ni < 4; ni++) {
            int row0 = bm + wm + mi * 16 + g;
            int col  = bn + wn + ni * 8 + t2;
            float* d = acc[mi][ni];
            if (MODE == 3) {
                float* C = (float*)Cv + sC * bz;
                float ax0 = 0.f, ax1 = 0.f;
                if (addx) {
                    float2 a = *(const float2*)&aux[sAux * bz + col];
                    ax0 = a.x; ax1 = a.y;
                }
                *(float2*)&C[(size_t)row0 * ldC + col] =
                    make_float2(d[0] + ax0, d[1] + ax1);
                *(float2*)&C[(size_t)(row0 + 8) * ldC + col] =
                    make_float2(d[2] + ax0, d[3] + ax1);
            } else {
                __nv_bfloat16* C = (__nv_bfloat16*)Cv + sC * bz;
                const float* ax = aux + sAux * bz;
                float2 a0 = *(const float2*)&ax[(size_t)row0 * ldC + col];
                float2 a1 = *(const float2*)&ax[(size_t)(row0 + 8) * ldC + col];
                *(__nv_bfloat162*)&C[(size_t)row0 * ldC + col] =
                    __floats2bfloat162_rn(a0.x + 0.1f * d[0], a0.y + 0.1f * d[1]);
                *(__nv_bfloat162*)&C[(size_t)(row0 + 8) * ldC + col] =
                    __floats2bfloat162_rn(a1.x + 0.1f * d[2], a1.y + 0.1f * d[3]);
            }
        }
    }
}

// ---------------- G2: dual-accumulator folded irfft, fused mirror + residual ----------------
#define BM2 128
#define BN2 64
#define BK2 32
#define NST2 3
#define A2_BYTES (256 * 40 * 2)    // 20480
#define B2_BYTES (64 * 72 * 2)     // 9216
#define G2_SMEM (NST2 * (A2_BYTES + B2_BYTES))   // 89088

__global__ __launch_bounds__(256, 2) void gemm_g2(
    const float* __restrict__ x, float* __restrict__ out)
{
    extern __shared__ __align__(16) char dsm[];

    int bz = blockIdx.z;
    int s0 = blockIdx.y * BM2;
    int n0 = blockIdx.x * BN2;
    const __nv_bfloat16* Adel = g_delta + (size_t)bz * K2 * DD;
    const float* xb = x + (size_t)bz * SS * DD;
    float* ob = out + (size_t)bz * SS * DD;

    int tid = threadIdx.x, lane = tid & 31, warp = tid >> 5;
    int wm = (warp & 3) * 32;
    int wn = (warp >> 2) * 32;

    float acc_c[2][4][4], acc_s[2][4][4];
#pragma unroll
    for (int i = 0; i < 2; i++)
#pragma unroll
        for (int j = 0; j < 4; j++)
#pragma unroll
            for (int c = 0; c < 4; c++) { acc_c[i][j][c] = 0.f; acc_s[i][j][c] = 0.f; }

    auto st_base = [&](int st) -> char* { return dsm + st * (A2_BYTES + B2_BYTES); };

    auto load_stage = [&](int s) {
        char* ap = st_base(s % NST2);
        char* bp = ap + A2_BYTES;
        int k0 = s * BK2;
#pragma unroll
        for (int i = 0; i < 4; i++) {
            int c = tid + i * 256;
            int row = c >> 2, col = (c & 3) << 3;
            int srow = (row < 128) ? (s0 + row) : (SH + s0 + row - 128);
            cp_async16(ap + (row * 40 + col) * 2, g_basis2f + (size_t)srow * KK + k0 + col);
        }
#pragma unroll
        for (int i = 0; i < 2; i++) {
            int c = tid + i * 256;
            int row = c >> 3, col = (c & 7) << 3;
            int drow = (row < 32) ? (k0 + row) : (KK + k0 + row - 32);
            cp_async16(bp + (row * 72 + col) * 2, Adel + (size_t)drow * DD + n0 + col);
        }
        cp_commit();
    };

    load_stage(0);
    load_stage(1);

    const int nt = KK / BK2;   // 8
    for (int kt = 0; kt < nt; kt++) {
        cp_wait<1>();
        __syncthreads();
        if (kt + 2 < nt) load_stage(kt + 2);
        else             cp_commit();

        char* ap = st_base(kt % NST2);
        char* bp = ap + A2_BYTES;

#pragma unroll
        for (int kk = 0; kk < BK2; kk += 16) {
            uint32_t afc[2][4], afs[2][4], bfr[4][2], bfi[4][2];
            int ar = wm + (lane & 15);
            int ac = kk + ((lane >> 4) << 3);
#pragma unroll
            for (int mi = 0; mi < 2; mi++) {
                uint32_t a1 = smem_u32(ap + ((ar + mi * 16) * 40 + ac) * 2);
                asm volatile("ldmatrix.sync.aligned.m8n8.x4.shared.b16 {%0,%1,%2,%3}, [%4];"
                             : "=r"(afc[mi][0]), "=r"(afc[mi][1]), "=r"(afc[mi][2]), "=r"(afc[mi][3])
                             : "r"(a1));
                uint32_t a2 = smem_u32(ap + ((128 + ar + mi * 16) * 40 + ac) * 2);
                asm volatile("ldmatrix.sync.aligned.m8n8.x4.shared.b16 {%0,%1,%2,%3}, [%4];"
                             : "=r"(afs[mi][0]), "=r"(afs[mi][1]), "=r"(afs[mi][2]), "=r"(afs[mi][3])
                             : "r"(a2));
            }
            int br = kk + (lane & 15);
#pragma unroll
            for (int ni = 0; ni < 4; ni++) {
                uint32_t b1 = smem_u32(bp + (br * 72 + wn + ni * 8) * 2);
                asm volatile("ldmatrix.sync.aligned.m8n8.x2.trans.shared.b16 {%0,%1}, [%2];"
                             : "=r"(bfr[ni][0]), "=r"(bfr[ni][1]) : "r"(b1));
                uint32_t b2 = smem_u32(bp + ((32 + br) * 72 + wn + ni * 8) * 2);
                asm volatile("ldmatrix.sync.aligned.m8n8.x2.trans.shared.b16 {%0,%1}, [%2];"
                             : "=r"(bfi[ni][0]), "=r"(bfi[ni][1]) : "r"(b2));
            }
#pragma unroll
            for (int mi = 0; mi < 2; mi++)
#pragma unroll
                for (int ni = 0; ni < 4; ni++) {
                    float* dc = acc_c[mi][ni];
                    asm volatile(
                        "mma.sync.aligned.m16n8k16.row.col.f32.bf16.bf16.f32 "
                        "{%0,%1,%2,%3}, {%4,%5,%6,%7}, {%8,%9}, {%0,%1,%2,%3};"
                        : "+f"(dc[0]), "+f"(dc[1]), "+f"(dc[2]), "+f"(dc[3])
                        : "r"(afc[mi][0]), "r"(afc[mi][1]), "r"(afc[mi][2]), "r"(afc[mi][3]),
                          "r"(bfr[ni][0]), "r"(bfr[ni][1]));
                    float* ds = acc_s[mi][ni];
                    asm volatile(
                        "mma.sync.aligned.m16n8k16.row.col.f32.bf16.bf16.f32 "
                        "{%0,%1,%2,%3}, {%4,%5,%6,%7}, {%8,%9}, {%0,%1,%2,%3};"
                        : "+f"(ds[0]), "+f"(ds[1]), "+f"(ds[2]), "+f"(ds[3])
                        : "r"(afs[mi][0]), "r"(afs[mi][1]), "r"(afs[mi][2]), "r"(afs[mi][3]),
                          "r"(bfi[ni][0]), "r"(bfi[ni][1]));
                }
        }
    }

    int g = lane >> 2, t2 = (lane & 3) << 1;
#pragma unroll
    for (int mi = 0; mi < 2; mi++) {
#pragma unroll
        for (int ni = 0; ni < 4; ni++) {
            float* dc = acc_c[mi][ni];
            float* ds = acc_s[mi][ni];
            int col = n0 + wn + ni * 8 + t2;
#pragma unroll
            for (int h = 0; h < 2; h++) {
                int s = s0 + wm + mi * 16 + g + h * 8;
                float vc0 = dc[2 * h], vc1 = dc[2 * h + 1];
                float vs0 = ds[2 * h], vs1 = ds[2 * h + 1];
                float2 xv = *(const float2*)(xb + (size_t)s * DD + col);
                *(float2*)(ob + (size_t)s * DD + col) =
                    make_float2(vc0 + vs0 + 2.f * xv.x, vc1 + vs1 + 2.f * xv.y);
                if (s > 0) {
                    float2 xm = *(const float2*)(xb + (size_t)(SS - s) * DD + col);
                    *(float2*)(ob + (size_t)(SS - s) * DD + col) =
                        make_float2(vc0 - vs0 + 2.f * xm.x, vc1 - vs1 + 2.f * xm.y);
                }
            }
        }
    }
}

// ---------------- row 1024 (Nyquist-fold row): pre-LN value ----------------
__global__ void k_row1024(const float* __restrict__ x, float* __restrict__ out) {
    int b = blockIdx.y;
    int c = blockIdx.x * 256 + threadIdx.x;
    const __nv_bfloat16* dr = g_delta + (size_t)b * K2 * DD;
    float acc = 0.f;
#pragma unroll 4
    for (int k = 0; k < KK; k++) {
        int f = freq_of(k);
        float w = ((f == 0) ? 1.0f : 2.0f) * (1.0f / (float)NFFT);
        if (f & 1) w = -w;
        acc += w * __bfloat162float(dr[(size_t)k * DD + c]);
    }
    size_t o = ((size_t)b * SS + SH) * DD + c;
    out[o] = acc + 2.f * x[o];
}

// ---------------- LayerNorm over D=1024, in place ----------------
__global__ void k_ln(float* __restrict__ y, const float* __restrict__ gamma,
                     const float* __restrict__ beta) {
    int row = blockIdx.x;
    float4* p = (float4*)(y + (size_t)row * DD);
    int t = threadIdx.x;
    float4 v = p[t];
    float s1 = v.x + v.y + v.z + v.w;
    float s2 = v.x * v.x + v.y * v.y + v.z * v.z + v.w * v.w;
#pragma unroll
    for (int o = 16; o > 0; o >>= 1) {
        s1 += __shfl_down_sync(0xffffffffu, s1, o);
        s2 += __shfl_down_sync(0xffffffffu, s2, o);
    }
    __shared__ float r1[8], r2[8];
    int w = t >> 5, l = t & 31;
    if (l == 0) { r1[w] = s1; r2[w] = s2; }
    __syncthreads();
    float mu = 0.f, m2 = 0.f;
#pragma unroll
    for (int i = 0; i < 8; i++) { mu += r1[i]; m2 += r2[i]; }
    mu *= (1.0f / (float)DD);
    float var = m2 * (1.0f / (float)DD) - mu * mu;
    float rs = rsqrtf(var + 1e-5f);
    float4 g = ((const float4*)gamma)[t];
    float4 bb = ((const float4*)beta)[t];
    v.x = (v.x - mu) * rs * g.x + bb.x;
    v.y = (v.y - mu) * rs * g.y + bb.y;
    v.z = (v.z - mu) * rs * g.z + bb.z;
    v.w = (v.w - mu) * rs * g.w + bb.w;
    p[t] = v;
}

// ---------------- launch ----------------
extern "C" void kernel_launch(void* const* d_in, const int* in_sizes, int n_in,
                              void* d_out, int out_size) {
    const float* x     = (const float*)d_in[0];
    const float* mag   = (const float*)d_in[1];
    const float* ph    = (const float*)d_in[2];
    const float* W     = (const float*)d_in[3];
    const float* gamma = (const float*)d_in[4];
    const float* beta  = (const float*)d_in[5];
    float* out = (float*)d_out;

    void *p_b1, *p_wt, *p_xc, *p_xd, *p_X, *p_xwr, *p_dp, *p_dl;
    cudaGetSymbolAddress(&p_b1, g_basis1f);
    cudaGetSymbolAddress(&p_wt, g_wt);
    cudaGetSymbolAddress(&p_xc, g_xc);
    cudaGetSymbolAddress(&p_xd, g_xd);
    cudaGetSymbolAddress(&p_X, g_X);
    cudaGetSymbolAddress(&p_xwr, g_xwr);
    cudaGetSymbolAddress(&p_dp, g_dpart);
    cudaGetSymbolAddress(&p_dl, g_delta);

    cudaFuncSetAttribute(gemm_mma<1>, cudaFuncAttributeMaxDynamicSharedMemorySize, GEMM_SMEM);
    cudaFuncSetAttribute(gemm_mma<3>, cudaFuncAttributeMaxDynamicSharedMemorySize, GEMM_SMEM);
    cudaFuncSetAttribute(gemm_g2, cudaFuncAttributeMaxDynamicSharedMemorySize, G2_SMEM);

    // 1. precompute: table, merged basis/wt/cw, fold
    k_tbl<<<NFFT / 256, 256>>>();
    k_pre<<<(N_CW + 255) / 256, 256>>>(W, mag, ph);
    k_fold<<<(BB * SH * (DD / 4)) / 256, 256>>>(x);

    // 2. G1 (folded): X[b] (512x1024) = basis1f (512x1024) @ {xc | xd}[b], +x0 on cos tiles
    gemm_mma<3><<<dim3(DD / BN, K2 / BM, BB), 256, GEMM_SMEM>>>(
        (const __nv_bfloat16*)p_b1, SH,
        (const __nv_bfloat16*)p_xc, (const __nv_bfloat16*)p_xd, (size_t)SH * DD, DD,
        p_X, (size_t)K2 * DD, DD,
        x, (size_t)SS * DD,
        SH, /*bsel=*/2);

    // 3. elementwise complex weighting (table-driven)
    k_elem<<<(BB * KK * DD) / 256, 256>>>();

    // 4. interference: deltar[b] = dpart + 0.1 * (WT @ xwr[b])
    gemm_mma<1><<<dim3(DD / BN, KK / BM, BB), 256, GEMM_SMEM>>>(
        (const __nv_bfloat16*)p_wt, KK,
        (const __nv_bfloat16*)p_xwr, (const __nv_bfloat16*)p_xwr, (size_t)KK * DD, DD,
        p_dl, (size_t)K2 * DD, DD,
        (const float*)p_dp, (size_t)KK * DD,
        KK, /*bsel=*/8);

    // 5. row 1024 (reads deltar)
    k_row1024<<<dim3(4, BB), 256>>>(x, out);

    // 6. G2 fused: out rows 0..1023, 1025..2047 (pre-LN), mirror + residual inline
    gemm_g2<<<dim3(DD / BN2, SH / BM2, BB), 256, G2_SMEM>>>(x, out);

    // 7. LayerNorm in place
    k_ln<<<BB * SS, 256>>>(out, gamma, beta);
}

// round 10
// speedup vs baseline: 1.0709x; 1.0017x over previous
#include <cuda_runtime.h>
#include <cuda_bf16.h>
#include <cstdint>
#include <cstdio>

// Problem constants
#define BB   8
#define SS   2048
#define DD   1024
#define KK   256
#define NFFT 2048
#define K2   512
#define SH   1024   // folded length

// ---------------- device scratch ----------------
__device__ __align__(256) float2        g_tbl[NFFT];              // cos/sin table
__device__ __align__(256) __nv_bfloat16 g_basis1f[K2 * SH];       // rows 0..255 cos(f*s), 256..511 -sin(f*s); col = s-1
__device__ __align__(256) __nv_bfloat16 g_basis2f[2 * SH * KK];   // rows 0..1023 (c/N)cos, rows 1024..2047 -(c/N)sin
__device__ __align__(256) __nv_bfloat16 g_wt[KK * KK];            // WT[j][k] = W[k][j]
__device__ __align__(256) float         g_cwr[KK * DD];           // mag*cos(ph)
__device__ __align__(256) float         g_cwi[KK * DD];           // mag*sin(ph)
__device__ __align__(256) __nv_bfloat16 g_xc[BB * SH * DD];       // x_s + x_{2048-s}
__device__ __align__(256) __nv_bfloat16 g_xd[BB * SH * DD];       // x_s - x_{2048-s}
__device__ __align__(256) float         g_X[BB * K2 * DD];        // Xr rows 0..255, Xi rows 256..511
__device__ __align__(256) __nv_bfloat16 g_xwr[BB * KK * DD];      // Re(x_weighted)
__device__ __align__(256) float         g_dpart[BB * KK * DD];    // xwr - Xr
__device__ __align__(256) __nv_bfloat16 g_delta[BB * K2 * DD];    // [deltar; deltai]
__device__ __align__(256) float         g_ycs[BB * 2 * SH * DD];  // rows 0..1023 ycos, 1024..2047 ysin

// ---------------- helpers ----------------
__device__ __forceinline__ int freq_of(int k) {
    if (k == 255) return 512;
    return (int)((double)k * (512.0 / 255.0));
}
__device__ __forceinline__ uint32_t smem_u32(const void* p) {
    return (uint32_t)__cvta_generic_to_shared(p);
}
__device__ __forceinline__ void cp_async16(void* smem_dst, const void* gmem_src) {
    asm volatile("cp.async.cg.shared.global [%0], [%1], 16;\n"
                 :: "r"(smem_u32(smem_dst)), "l"(gmem_src));
}
__device__ __forceinline__ void cp_commit() {
    asm volatile("cp.async.commit_group;\n");
}
template <int N>
__device__ __forceinline__ void cp_wait() {
    asm volatile("cp.async.wait_group %0;\n" :: "n"(N));
}

// ---------------- precompute ----------------
__global__ void k_tbl() {
    int m = blockIdx.x * blockDim.x + threadIdx.x;
    float ang = (float)m * (6.28318530717958647692f / (float)NFFT);
    float sv, cv;
    sincosf(ang, &sv, &cv);
    g_tbl[m] = make_float2(cv, sv);
}

// merged precompute: basis1f, basis2f, wt, cw
#define N_B1 (K2 * SH)
#define N_B2 (N_B1 + 2 * SH * KK)
#define N_WT (N_B2 + KK * KK)
#define N_CW (N_WT + KK * DD)
__global__ void k_pre(const float* __restrict__ W,
                      const float* __restrict__ mag, const float* __restrict__ ph) {
    int idx = blockIdx.x * blockDim.x + threadIdx.x;
    if (idx < N_B1) {
        int row = idx >> 10;             // 0..511
        int s   = (idx & 1023) + 1;      // 1..1024
        int f   = freq_of(row & 255);
        float2 t = g_tbl[(f * s) & (NFFT - 1)];
        g_basis1f[idx] = __float2bfloat16((row < KK) ? t.x : -t.y);
    } else if (idx < N_B2) {
        int i = idx - N_B1;
        int row = i >> 8;                // 0..2047
        int j   = i & 255;
        int s   = row & 1023;
        int f   = freq_of(j);
        float2 t = g_tbl[(f * s) & (NFFT - 1)];
        float scale = ((f == 0) ? 1.0f : 2.0f) * (1.0f / (float)NFFT);
        g_basis2f[i] = __float2bfloat16((row < SH) ? (scale * t.x) : (-scale * t.y));
    } else if (idx < N_WT) {
        int i = idx - N_B2;
        int j = i >> 8, k = i & 255;
        g_wt[i] = __float2bfloat16(W[k * KK + j]);
    } else if (idx < N_CW) {
        int i = idx - N_WT;
        float sp, cp;
        sincosf(ph[i], &sp, &cp);
        float m = mag[i];
        g_cwr[i] = m * cp;
        g_cwi[i] = m * sp;
    }
}

// ---------------- fold ----------------
__global__ void k_fold(const float* __restrict__ x) {
    int idx = blockIdx.x * blockDim.x + threadIdx.x;
    if (idx >= BB * SH * (DD / 4)) return;
    int b   = idx >> 18;
    int r   = idx & 262143;
    int srow = r >> 8;
    int d4   = (r & 255) << 2;
    int s = srow + 1;
    const float* xb = x + (size_t)b * SS * DD;
    float4 xs = *(const float4*)(xb + (size_t)s * DD + d4);
    float4 c, d;
    if (s == 1024) {
        c = xs;
        d = make_float4(0.f, 0.f, 0.f, 0.f);
    } else {
        float4 xm = *(const float4*)(xb + (size_t)(SS - s) * DD + d4);
        c = make_float4(xs.x + xm.x, xs.y + xm.y, xs.z + xm.z, xs.w + xm.w);
        d = make_float4(xs.x - xm.x, xs.y - xm.y, xs.z - xm.z, xs.w - xm.w);
    }
    size_t o = ((size_t)b * SH + srow) * DD + d4;
    *(__nv_bfloat162*)&g_xc[o]     = __floats2bfloat162_rn(c.x, c.y);
    *(__nv_bfloat162*)&g_xc[o + 2] = __floats2bfloat162_rn(c.z, c.w);
    *(__nv_bfloat162*)&g_xd[o]     = __floats2bfloat162_rn(d.x, d.y);
    *(__nv_bfloat162*)&g_xd[o + 2] = __floats2bfloat162_rn(d.z, d.w);
}

// ---------------- elementwise complex weighting (table-driven, no sincos) ----------------
__global__ void k_elem() {
    int idx = blockIdx.x * blockDim.x + threadIdx.x;
    if (idx >= BB * KK * DD) return;
    int b = idx >> 18;
    int r = idx & 262143;   // k*1024 + d
    size_t xb = (size_t)b * (K2 * DD);
    float Xr = g_X[xb + r];
    float Xi = g_X[xb + (KK * DD) + r];
    float cr = g_cwr[r];
    float ci = g_cwi[r];
    float xwr = Xr * cr - Xi * ci;
    float xwi = Xr * ci + Xi * cr;
    g_xwr[idx]   = __float2bfloat16(xwr);
    g_dpart[idx] = xwr - Xr;
    g_delta[xb + (KK * DD) + r] = __float2bfloat16(xwi - Xi);
}

// ---------------- standard GEMM engine (G1 folded, interference, G2), 4-stage ----------------
#define BM 128
#define BN 128
#define BKg 32
#define NSTG 4
#define A_BYTES (BM * 40 * 2)
#define B_BYTES (BKg * 136 * 2)
#define GEMM_SMEM (NSTG * (A_BYTES + B_BYTES))

// MODE 1: bf16 store: aux + 0.1*acc  (interference)
// MODE 3: fp32 store: acc (+ aux_row0[col] if aux && by<bsel)
template <int MODE>
__global__ __launch_bounds__(256, 2) void gemm_mma(
    const __nv_bfloat16* __restrict__ A, int ldA,
    const __nv_bfloat16* __restrict__ B0, const __nv_bfloat16* __restrict__ B1,
    size_t sB, int ldB,
    void* __restrict__ Cv, size_t sC, int ldC,
    const float* __restrict__ aux, size_t sAux,
    int Kdim, int bsel)
{
    extern __shared__ __align__(16) char dsm[];

    int bz = blockIdx.z;
    int bm = blockIdx.y * BM;
    int bn = blockIdx.x * BN;
    const __nv_bfloat16* Ab = A;
    const __nv_bfloat16* Bb = ((int)blockIdx.y < bsel ? B0 : B1) + sB * bz;

    int tid = threadIdx.x, lane = tid & 31, warp = tid >> 5;
    int wm = (warp & 1) * 64;
    int wn = (warp >> 1) * 32;

    int a_r0 = tid >> 2;
    int a_c  = (tid & 3) << 3;
    int b_r0 = tid >> 4;
    int b_c  = (tid & 15) << 3;

    float acc[4][4][4];
#pragma unroll
    for (int i = 0; i < 4; i++)
#pragma unroll
        for (int j = 0; j < 4; j++)
#pragma unroll
            for (int c = 0; c < 4; c++) acc[i][j][c] = 0.f;

    int nt = Kdim / BKg;

    auto a_base = [&](int st) -> char* { return dsm + st * A_BYTES; };
    auto b_base = [&](int st) -> char* { return dsm + NSTG * A_BYTES + st * B_BYTES; };

    auto load_stage = [&](int s) {
        char* ap = a_base(s & (NSTG - 1));
        char* bp = b_base(s & (NSTG - 1));
        int k0 = s * BKg;
        cp_async16(ap + (a_r0 * 40 + a_c) * 2,        Ab + (size_t)(bm + a_r0) * ldA + k0 + a_c);
        cp_async16(ap + ((a_r0 + 64) * 40 + a_c) * 2, Ab + (size_t)(bm + a_r0 + 64) * ldA + k0 + a_c);
        cp_async16(bp + (b_r0 * 136 + b_c) * 2,        Bb + (size_t)(k0 + b_r0) * ldB + bn + b_c);
        cp_async16(bp + ((b_r0 + 16) * 136 + b_c) * 2, Bb + (size_t)(k0 + b_r0 + 16) * ldB + bn + b_c);
        cp_commit();
    };

#pragma unroll
    for (int i = 0; i < NSTG - 1; i++) load_stage(i);

    for (int kt = 0; kt < nt; kt++) {
        cp_wait<NSTG - 2>();
        __syncthreads();
        if (kt + NSTG - 1 < nt) load_stage(kt + NSTG - 1);
        else                    cp_commit();

        char* ap = a_base(kt & (NSTG - 1));
        char* bp = b_base(kt & (NSTG - 1));

#pragma unroll
        for (int kk = 0; kk < BKg; kk += 16) {
            uint32_t af[4][4], bf[4][2];
            int ar = wm + (lane & 15);
            int ac = kk + ((lane >> 4) << 3);
#pragma unroll
            for (int mi = 0; mi < 4; mi++) {
                uint32_t ad = smem_u32(ap + ((ar + mi * 16) * 40 + ac) * 2);
                asm volatile("ldmatrix.sync.aligned.m8n8.x4.shared.b16 {%0,%1,%2,%3}, [%4];"
                             : "=r"(af[mi][0]), "=r"(af[mi][1]), "=r"(af[mi][2]), "=r"(af[mi][3])
                             : "r"(ad));
            }
            int br = kk + (lane & 15);
#pragma unroll
            for (int ni = 0; ni < 4; ni++) {
                uint32_t bd = smem_u32(bp + (br * 136 + wn + ni * 8) * 2);
                asm volatile("ldmatrix.sync.aligned.m8n8.x2.trans.shared.b16 {%0,%1}, [%2];"
                             : "=r"(bf[ni][0]), "=r"(bf[ni][1]) : "r"(bd));
            }
#pragma unroll
            for (int mi = 0; mi < 4; mi++)
#pragma unroll
                for (int ni = 0; ni < 4; ni++) {
                    float* d = acc[mi][ni];
                    asm volatile(
                        "mma.sync.aligned.m16n8k16.row.col.f32.bf16.bf16.f32 "
                        "{%0,%1,%2,%3}, {%4,%5,%6,%7}, {%8,%9}, {%0,%1,%2,%3};"
                        : "+f"(d[0]), "+f"(d[1]), "+f"(d[2]), "+f"(d[3])
                        : "r"(af[mi][0]), "r"(af[mi][1]), "r"(af[mi][2]), "r"(af[mi][3]),
                          "r"(bf[ni][0]), "r"(bf[ni][1]));
                }
        }
    }

    int g = lane >> 2, t2 = (lane & 3) << 1;
    bool addx = (MODE == 3) && (aux != nullptr) && ((int)blockIdx.y < bsel);
#pragma unroll
    for (int mi = 0; mi < 4; mi++) {
#pragma unroll
        for (int ni = 0; ni < 4; ni++) {
            int row0 = bm + wm + mi * 16 + g;
            int col  = bn + wn + ni * 8 + t2;
            float* d = acc[mi][ni];
            if (MODE == 3) {
                float* C = (float*)Cv + sC * bz;
                float ax0 = 0.f, ax1 = 0.f;
                if (addx) {
                    float2 a = *(const float2*)&aux[sAux * bz + col];
                    ax0 = a.x; ax1 = a.y;
                }
                *(float2*)&C[(size_t)row0 * ldC + col] =
                    make_float2(d[0] + ax0, d[1] + ax1);
                *(float2*)&C[(size_t)(row0 + 8) * ldC + col] =
                    make_float2(d[2] + ax0, d[3] + ax1);
            } else {
                __nv_bfloat16* C = (__nv_bfloat16*)Cv + sC * bz;
                const float* ax = aux + sAux * bz;
                float2 a0 = *(const float2*)&ax[(size_t)row0 * ldC + col];
                float2 a1 = *(const float2*)&ax[(size_t)(row0 + 8) * ldC + col];
                *(__nv_bfloat162*)&C[(size_t)row0 * ldC + col] =
                    __floats2bfloat162_rn(a0.x + 0.1f * d[0], a0.y + 0.1f * d[1]);
                *(__nv_bfloat162*)&C[(size_t)(row0 + 8) * ldC + col] =
                    __floats2bfloat162_rn(a1.x + 0.1f * d[2], a1.y + 0.1f * d[3]);
            }
        }
    }
}

// ---------------- combine (mirror + residual + row1024) + LayerNorm, one pass ----------------
// blockIdx.x = rp in 0..1024, blockIdx.y = batch. 256 threads, 4 floats each.
__global__ __launch_bounds__(256) void k_combine(
    const float* __restrict__ x, float* __restrict__ out,
    const float* __restrict__ gamma, const float* __restrict__ beta)
{
    __shared__ float r1[8], r2[8];
    int b = blockIdx.y, rp = blockIdx.x, t = threadIdx.x;
    int w = t >> 5, l = t & 31;
    int d4 = t << 2;
    const float* xb = x + (size_t)b * SS * DD;
    const float* ycs = g_ycs + (size_t)b * 2 * SH * DD;
    float4 gmv = ((const float4*)gamma)[t];
    float4 btv = ((const float4*)beta)[t];

    float4 vc, vs, va;
    if (rp < SH) {
        vc = *(const float4*)(ycs + (size_t)rp * DD + d4);
        vs = *(const float4*)(ycs + (size_t)(SH + rp) * DD + d4);
        float4 xv = *(const float4*)(xb + (size_t)rp * DD + d4);
        va = make_float4(vc.x + vs.x + 2.f * xv.x, vc.y + vs.y + 2.f * xv.y,
                         vc.z + vs.z + 2.f * xv.z, vc.w + vs.w + 2.f * xv.w);
    } else {
        // rp == 1024: ycos_1024[d] = sum_k (c/N)(-1)^f deltar[k][d]
        float a0 = 0.f, a1 = 0.f, a2 = 0.f, a3 = 0.f;
        const __nv_bfloat16* dr = g_delta + (size_t)b * K2 * DD;
        for (int k = 0; k < KK; k++) {
            int f = freq_of(k);
            float wgt = ((f == 0) ? 1.0f : 2.0f) * (1.0f / (float)NFFT);
            if (f & 1) wgt = -wgt;
            __nv_bfloat162 p0 = *(const __nv_bfloat162*)(dr + (size_t)k * DD + d4);
            __nv_bfloat162 p1 = *(const __nv_bfloat162*)(dr + (size_t)k * DD + d4 + 2);
            a0 += wgt * __bfloat162float(p0.x);
            a1 += wgt * __bfloat162float(p0.y);
            a2 += wgt * __bfloat162float(p1.x);
            a3 += wgt * __bfloat162float(p1.y);
        }
        float4 xv = *(const float4*)(xb + (size_t)SH * DD + d4);
        va = make_float4(a0 + 2.f * xv.x, a1 + 2.f * xv.y,
                         a2 + 2.f * xv.z, a3 + 2.f * xv.w);
    }

    // --- LN row A ---
    {
        float s1 = va.x + va.y + va.z + va.w;
        float s2 = va.x * va.x + va.y * va.y + va.z * va.z + va.w * va.w;
#pragma unroll
        for (int o = 16; o > 0; o >>= 1) {
            s1 += __shfl_down_sync(0xffffffffu, s1, o);
            s2 += __shfl_down_sync(0xffffffffu, s2, o);
        }
        if (l == 0) { r1[w] = s1; r2[w] = s2; }
        __syncthreads();
        float mu = 0.f, m2 = 0.f;
#pragma unroll
        for (int i = 0; i < 8; i++) { mu += r1[i]; m2 += r2[i]; }
        mu *= (1.0f / (float)DD);
        float var = m2 * (1.0f / (float)DD) - mu * mu;
        float rs = rsqrtf(var + 1e-5f);
        float* op = out + ((size_t)b * SS + rp) * DD + d4;
        op[0] = (va.x - mu) * rs * gmv.x + btv.x;
        op[1] = (va.y - mu) * rs * gmv.y + btv.y;
        op[2] = (va.z - mu) * rs * gmv.z + btv.z;
        op[3] = (va.w - mu) * rs * gmv.w + btv.w;
    }

    // --- row B: mirror 2048-rp, rp in 1..1023 ---
    if (rp >= 1 && rp < SH) {
        float4 xv = *(const float4*)(xb + (size_t)(SS - rp) * DD + d4);
        float4 vb = make_float4(vc.x - vs.x + 2.f * xv.x, vc.y - vs.y + 2.f * xv.y,
                                vc.z - vs.z + 2.f * xv.z, vc.w - vs.w + 2.f * xv.w);
        float s1 = vb.x + vb.y + vb.z + vb.w;
        float s2 = vb.x * vb.x + vb.y * vb.y + vb.z * vb.z + vb.w * vb.w;
#pragma unroll
        for (int o = 16; o > 0; o >>= 1) {
            s1 += __shfl_down_sync(0xffffffffu, s1, o);
            s2 += __shfl_down_sync(0xffffffffu, s2, o);
        }
        __syncthreads();   // protect r1/r2 reuse
        if (l == 0) { r1[w] = s1; r2[w] = s2; }
        __syncthreads();
        float mu = 0.f, m2 = 0.f;
#pragma unroll
        for (int i = 0; i < 8; i++) { mu += r1[i]; m2 += r2[i]; }
        mu *= (1.0f / (float)DD);
        float var = m2 * (1.0f / (float)DD) - mu * mu;
        float rs = rsqrtf(var + 1e-5f);
        float* op = out + ((size_t)b * SS + (SS - rp)) * DD + d4;
        op[0] = (vb.x - mu) * rs * gmv.x + btv.x;
        op[1] = (vb.y - mu) * rs * gmv.y + btv.y;
        op[2] = (vb.z - mu) * rs * gmv.z + btv.z;
        op[3] = (vb.w - mu) * rs * gmv.w + btv.w;
    }
}

// ---------------- launch ----------------
extern "C" void kernel_launch(void* const* d_in, const int* in_sizes, int n_in,
                              void* d_out, int out_size) {
    const float* x     = (const float*)d_in[0];
    const float* mag   = (const float*)d_in[1];
    const float* ph    = (const float*)d_in[2];
    const float* W     = (const float*)d_in[3];
    const float* gamma = (const float*)d_in[4];
    const float* beta  = (const float*)d_in[5];
    float* out = (float*)d_out;

    void *p_b1, *p_b2, *p_wt, *p_xc, *p_xd, *p_X, *p_xwr, *p_dp, *p_dl, *p_ycs;
    cudaGetSymbolAddress(&p_b1, g_basis1f);
    cudaGetSymbolAddress(&p_b2, g_basis2f);
    cudaGetSymbolAddress(&p_wt, g_wt);
    cudaGetSymbolAddress(&p_xc, g_xc);
    cudaGetSymbolAddress(&p_xd, g_xd);
    cudaGetSymbolAddress(&p_X, g_X);
    cudaGetSymbolAddress(&p_xwr, g_xwr);
    cudaGetSymbolAddress(&p_dp, g_dpart);
    cudaGetSymbolAddress(&p_dl, g_delta);
    cudaGetSymbolAddress(&p_ycs, g_ycs);

    cudaFuncSetAttribute(gemm_mma<1>, cudaFuncAttributeMaxDynamicSharedMemorySize, GEMM_SMEM);
    cudaFuncSetAttribute(gemm_mma<3>, cudaFuncAttributeMaxDynamicSharedMemorySize, GEMM_SMEM);

    // 1. precompute: table, merged basis/wt/cw, fold
    k_tbl<<<NFFT / 256, 256>>>();
    k_pre<<<(N_CW + 255) / 256, 256>>>(W, mag, ph);
    k_fold<<<(BB * SH * (DD / 4)) / 256, 256>>>(x);

    // 2. G1 (folded): X[b] (512x1024) = basis1f (512x1024) @ {xc | xd}[b], +x0 on cos tiles
    gemm_mma<3><<<dim3(DD / BN, K2 / BM, BB), 256, GEMM_SMEM>>>(
        (const __nv_bfloat16*)p_b1, SH,
        (const __nv_bfloat16*)p_xc, (const __nv_bfloat16*)p_xd, (size_t)SH * DD, DD,
        p_X, (size_t)K2 * DD, DD,
        x, (size_t)SS * DD,
        SH, /*bsel=*/2);

    // 3. elementwise complex weighting (table-driven)
    k_elem<<<(BB * KK * DD) / 256, 256>>>();

    // 4. interference: deltar[b] = dpart + 0.1 * (WT @ xwr[b])
    gemm_mma<1><<<dim3(DD / BN, KK / BM, BB), 256, GEMM_SMEM>>>(
        (const __nv_bfloat16*)p_wt, KK,
        (const __nv_bfloat16*)p_xwr, (const __nv_bfloat16*)p_xwr, (size_t)KK * DD, DD,
        p_dl, (size_t)K2 * DD, DD,
        (const float*)p_dp, (size_t)KK * DD,
        KK, /*bsel=*/8);

    // 5. G2 (folded, standard engine): ycs[b] (2048x1024) = basis2f @ {deltar | deltai}[b]
    gemm_mma<3><<<dim3(DD / BN, (2 * SH) / BM, BB), 256, GEMM_SMEM>>>(
        (const __nv_bfloat16*)p_b2, KK,
        (const __nv_bfloat16*)p_dl, (const __nv_bfloat16*)p_dl + (size_t)KK * DD,
        (size_t)K2 * DD, DD,
        p_ycs, (size_t)2 * SH * DD, DD,
        nullptr, 0,
        KK, /*bsel=*/8);

    // 6. combine: mirror + residual + row1024 + LayerNorm, single pass
    k_combine<<<dim3(SH + 1, BB), 256>>>(x, out, gamma, beta);
}

// round 11
// speedup vs baseline: 1.1313x; 1.0564x over previous
#include <cuda_runtime.h>
#include <cuda_bf16.h>
#include <cstdint>
#include <cstdio>

// Problem constants
#define BB   8
#define SS   2048
#define DD   1024
#define KK   256
#define NFFT 2048
#define K2   512
#define SH   1024   // folded length
#define HB   4      // half batch (per chain)

// ---------------- device scratch ----------------
__device__ __align__(256) float2        g_tbl[NFFT];              // cos/sin table
__device__ __align__(256) __nv_bfloat16 g_basis1f[K2 * SH];       // rows 0..255 cos(f*s), 256..511 -sin(f*s); col = s-1
__device__ __align__(256) __nv_bfloat16 g_basis2f[2 * SH * KK];   // rows 0..1023 (c/N)cos, rows 1024..2047 -(c/N)sin
__device__ __align__(256) __nv_bfloat16 g_wt[KK * KK];            // WT[j][k] = W[k][j]
__device__ __align__(256) float         g_cwr[KK * DD];           // mag*cos(ph)
__device__ __align__(256) float         g_cwi[KK * DD];           // mag*sin(ph)
__device__ __align__(256) __nv_bfloat16 g_xc[BB * SH * DD];       // x_s + x_{2048-s}
__device__ __align__(256) __nv_bfloat16 g_xd[BB * SH * DD];       // x_s - x_{2048-s}
__device__ __align__(256) float         g_X[BB * K2 * DD];        // Xr rows 0..255, Xi rows 256..511
__device__ __align__(256) __nv_bfloat16 g_xwr[BB * KK * DD];      // Re(x_weighted)
__device__ __align__(256) float         g_dpart[BB * KK * DD];    // xwr - Xr
__device__ __align__(256) __nv_bfloat16 g_delta[BB * K2 * DD];    // [deltar; deltai]
__device__ __align__(256) float         g_ycs[BB * 2 * SH * DD];  // rows 0..1023 ycos, 1024..2047 ysin

// ---------------- helpers ----------------
__device__ __forceinline__ int freq_of(int k) {
    if (k == 255) return 512;
    return (int)((double)k * (512.0 / 255.0));
}
__device__ __forceinline__ uint32_t smem_u32(const void* p) {
    return (uint32_t)__cvta_generic_to_shared(p);
}
__device__ __forceinline__ void cp_async16(void* smem_dst, const void* gmem_src) {
    asm volatile("cp.async.cg.shared.global [%0], [%1], 16;\n"
                 :: "r"(smem_u32(smem_dst)), "l"(gmem_src));
}
__device__ __forceinline__ void cp_commit() {
    asm volatile("cp.async.commit_group;\n");
}
template <int N>
__device__ __forceinline__ void cp_wait() {
    asm volatile("cp.async.wait_group %0;\n" :: "n"(N));
}

// ---------------- precompute ----------------
__global__ void k_tbl() {
    int m = blockIdx.x * blockDim.x + threadIdx.x;
    float ang = (float)m * (6.28318530717958647692f / (float)NFFT);
    float sv, cv;
    sincosf(ang, &sv, &cv);
    g_tbl[m] = make_float2(cv, sv);
}

// merged precompute: basis1f, basis2f, wt, cw
#define N_B1 (K2 * SH)
#define N_B2 (N_B1 + 2 * SH * KK)
#define N_WT (N_B2 + KK * KK)
#define N_CW (N_WT + KK * DD)
__global__ void k_pre(const float* __restrict__ W,
                      const float* __restrict__ mag, const float* __restrict__ ph) {
    int idx = blockIdx.x * blockDim.x + threadIdx.x;
    if (idx < N_B1) {
        int row = idx >> 10;             // 0..511
        int s   = (idx & 1023) + 1;      // 1..1024
        int f   = freq_of(row & 255);
        float2 t = g_tbl[(f * s) & (NFFT - 1)];
        g_basis1f[idx] = __float2bfloat16((row < KK) ? t.x : -t.y);
    } else if (idx < N_B2) {
        int i = idx - N_B1;
        int row = i >> 8;                // 0..2047
        int j   = i & 255;
        int s   = row & 1023;
        int f   = freq_of(j);
        float2 t = g_tbl[(f * s) & (NFFT - 1)];
        float scale = ((f == 0) ? 1.0f : 2.0f) * (1.0f / (float)NFFT);
        g_basis2f[i] = __float2bfloat16((row < SH) ? (scale * t.x) : (-scale * t.y));
    } else if (idx < N_WT) {
        int i = idx - N_B2;
        int j = i >> 8, k = i & 255;
        g_wt[i] = __float2bfloat16(W[k * KK + j]);
    } else if (idx < N_CW) {
        int i = idx - N_WT;
        float sp, cp;
        sincosf(ph[i], &sp, &cp);
        float m = mag[i];
        g_cwr[i] = m * cp;
        g_cwi[i] = m * sp;
    }
}

// ---------------- fold (all batches) ----------------
__global__ void k_fold(const float* __restrict__ x) {
    int idx = blockIdx.x * blockDim.x + threadIdx.x;
    if (idx >= BB * SH * (DD / 4)) return;
    int b   = idx >> 18;
    int r   = idx & 262143;
    int srow = r >> 8;
    int d4   = (r & 255) << 2;
    int s = srow + 1;
    const float* xb = x + (size_t)b * SS * DD;
    float4 xs = *(const float4*)(xb + (size_t)s * DD + d4);
    float4 c, d;
    if (s == 1024) {
        c = xs;
        d = make_float4(0.f, 0.f, 0.f, 0.f);
    } else {
        float4 xm = *(const float4*)(xb + (size_t)(SS - s) * DD + d4);
        c = make_float4(xs.x + xm.x, xs.y + xm.y, xs.z + xm.z, xs.w + xm.w);
        d = make_float4(xs.x - xm.x, xs.y - xm.y, xs.z - xm.z, xs.w - xm.w);
    }
    size_t o = ((size_t)b * SH + srow) * DD + d4;
    *(__nv_bfloat162*)&g_xc[o]     = __floats2bfloat162_rn(c.x, c.y);
    *(__nv_bfloat162*)&g_xc[o + 2] = __floats2bfloat162_rn(c.z, c.w);
    *(__nv_bfloat162*)&g_xd[o]     = __floats2bfloat162_rn(d.x, d.y);
    *(__nv_bfloat162*)&g_xd[o + 2] = __floats2bfloat162_rn(d.z, d.w);
}

// ---------------- elementwise complex weighting (half batch, offset b0) ----------------
__global__ void k_elem(int b0) {
    int idx = blockIdx.x * blockDim.x + threadIdx.x;
    if (idx >= HB * KK * DD) return;
    int b = (idx >> 18) + b0;
    int r = idx & 262143;   // k*1024 + d
    size_t xb = (size_t)b * (K2 * DD);
    size_t o1 = ((size_t)b << 18) + r;
    float Xr = g_X[xb + r];
    float Xi = g_X[xb + (KK * DD) + r];
    float cr = g_cwr[r];
    float ci = g_cwi[r];
    float xwr = Xr * cr - Xi * ci;
    float xwi = Xr * ci + Xi * cr;
    g_xwr[o1]   = __float2bfloat16(xwr);
    g_dpart[o1] = xwr - Xr;
    g_delta[xb + (KK * DD) + r] = __float2bfloat16(xwi - Xi);
}

// ---------------- standard GEMM engine, 4-stage, batch-offset ----------------
#define BM 128
#define BN 128
#define BKg 32
#define NSTG 4
#define A_BYTES (BM * 40 * 2)
#define B_BYTES (BKg * 136 * 2)
#define GEMM_SMEM (NSTG * (A_BYTES + B_BYTES))

// MODE 1: bf16 store: aux + 0.1*acc  (interference)
// MODE 3: fp32 store: acc (+ aux_row0[col] if aux && by<bsel)
template <int MODE>
__global__ __launch_bounds__(256, 2) void gemm_mma(
    const __nv_bfloat16* __restrict__ A, int ldA,
    const __nv_bfloat16* __restrict__ B0, const __nv_bfloat16* __restrict__ B1,
    size_t sB, int ldB,
    void* __restrict__ Cv, size_t sC, int ldC,
    const float* __restrict__ aux, size_t sAux,
    int Kdim, int bsel, int b0)
{
    extern __shared__ __align__(16) char dsm[];

    int bz = blockIdx.z + b0;
    int bm = blockIdx.y * BM;
    int bn = blockIdx.x * BN;
    const __nv_bfloat16* Ab = A;
    const __nv_bfloat16* Bb = ((int)blockIdx.y < bsel ? B0 : B1) + sB * bz;

    int tid = threadIdx.x, lane = tid & 31, warp = tid >> 5;
    int wm = (warp & 1) * 64;
    int wn = (warp >> 1) * 32;

    int a_r0 = tid >> 2;
    int a_c  = (tid & 3) << 3;
    int b_r0 = tid >> 4;
    int b_c  = (tid & 15) << 3;

    float acc[4][4][4];
#pragma unroll
    for (int i = 0; i < 4; i++)
#pragma unroll
        for (int j = 0; j < 4; j++)
#pragma unroll
            for (int c = 0; c < 4; c++) acc[i][j][c] = 0.f;

    int nt = Kdim / BKg;

    auto a_base = [&](int st) -> char* { return dsm + st * A_BYTES; };
    auto b_base = [&](int st) -> char* { return dsm + NSTG * A_BYTES + st * B_BYTES; };

    auto load_stage = [&](int s) {
        char* ap = a_base(s & (NSTG - 1));
        char* bp = b_base(s & (NSTG - 1));
        int k0 = s * BKg;
        cp_async16(ap + (a_r0 * 40 + a_c) * 2,        Ab + (size_t)(bm + a_r0) * ldA + k0 + a_c);
        cp_async16(ap + ((a_r0 + 64) * 40 + a_c) * 2, Ab + (size_t)(bm + a_r0 + 64) * ldA + k0 + a_c);
        cp_async16(bp + (b_r0 * 136 + b_c) * 2,        Bb + (size_t)(k0 + b_r0) * ldB + bn + b_c);
        cp_async16(bp + ((b_r0 + 16) * 136 + b_c) * 2, Bb + (size_t)(k0 + b_r0 + 16) * ldB + bn + b_c);
        cp_commit();
    };

#pragma unroll
    for (int i = 0; i < NSTG - 1; i++) load_stage(i);

    for (int kt = 0; kt < nt; kt++) {
        cp_wait<NSTG - 2>();
        __syncthreads();
        if (kt + NSTG - 1 < nt) load_stage(kt + NSTG - 1);
        else                    cp_commit();

        char* ap = a_base(kt & (NSTG - 1));
        char* bp = b_base(kt & (NSTG - 1));

#pragma unroll
        for (int kk = 0; kk < BKg; kk += 16) {
            uint32_t af[4][4], bf[4][2];
            int ar = wm + (lane & 15);
            int ac = kk + ((lane >> 4) << 3);
#pragma unroll
            for (int mi = 0; mi < 4; mi++) {
                uint32_t ad = smem_u32(ap + ((ar + mi * 16) * 40 + ac) * 2);
                asm volatile("ldmatrix.sync.aligned.m8n8.x4.shared.b16 {%0,%1,%2,%3}, [%4];"
                             : "=r"(af[mi][0]), "=r"(af[mi][1]), "=r"(af[mi][2]), "=r"(af[mi][3])
                             : "r"(ad));
            }
            int br = kk + (lane & 15);
#pragma unroll
            for (int ni = 0; ni < 4; ni++) {
                uint32_t bd = smem_u32(bp + (br * 136 + wn + ni * 8) * 2);
                asm volatile("ldmatrix.sync.aligned.m8n8.x2.trans.shared.b16 {%0,%1}, [%2];"
                             : "=r"(bf[ni][0]), "=r"(bf[ni][1]) : "r"(bd));
            }
#pragma unroll
            for (int mi = 0; mi < 4; mi++)
#pragma unroll
                for (int ni = 0; ni < 4; ni++) {
                    float* d = acc[mi][ni];
                    asm volatile(
                        "mma.sync.aligned.m16n8k16.row.col.f32.bf16.bf16.f32 "
                        "{%0,%1,%2,%3}, {%4,%5,%6,%7}, {%8,%9}, {%0,%1,%2,%3};"
                        : "+f"(d[0]), "+f"(d[1]), "+f"(d[2]), "+f"(d[3])
                        : "r"(af[mi][0]), "r"(af[mi][1]), "r"(af[mi][2]), "r"(af[mi][3]),
                          "r"(bf[ni][0]), "r"(bf[ni][1]));
                }
        }
    }

    int g = lane >> 2, t2 = (lane & 3) << 1;
    bool addx = (MODE == 3) && (aux != nullptr) && ((int)blockIdx.y < bsel);
#pragma unroll
    for (int mi = 0; mi < 4; mi++) {
#pragma unroll
        for (int ni = 0; ni < 4; ni++) {
            int row0 = bm + wm + mi * 16 + g;
            int col  = bn + wn + ni * 8 + t2;
            float* d = acc[mi][ni];
            if (MODE == 3) {
                float* C = (float*)Cv + sC * bz;
                float ax0 = 0.f, ax1 = 0.f;
                if (addx) {
                    float2 a = *(const float2*)&aux[sAux * bz + col];
                    ax0 = a.x; ax1 = a.y;
                }
                *(float2*)&C[(size_t)row0 * ldC + col] =
                    make_float2(d[0] + ax0, d[1] + ax1);
                *(float2*)&C[(size_t)(row0 + 8) * ldC + col] =
                    make_float2(d[2] + ax0, d[3] + ax1);
            } else {
                __nv_bfloat16* C = (__nv_bfloat16*)Cv + sC * bz;
                const float* ax = aux + sAux * bz;
                float2 a0 = *(const float2*)&ax[(size_t)row0 * ldC + col];
                float2 a1 = *(const float2*)&ax[(size_t)(row0 + 8) * ldC + col];
                *(__nv_bfloat162*)&C[(size_t)row0 * ldC + col] =
                    __floats2bfloat162_rn(a0.x + 0.1f * d[0], a0.y + 0.1f * d[1]);
                *(__nv_bfloat162*)&C[(size_t)(row0 + 8) * ldC + col] =
                    __floats2bfloat162_rn(a1.x + 0.1f * d[2], a1.y + 0.1f * d[3]);
            }
        }
    }
}

// ---------------- combine (mirror + residual + row1024) + LayerNorm ----------------
// blockIdx.x = rp in 0..1024, blockIdx.y = local batch (+b0). 256 threads.
__global__ __launch_bounds__(256) void k_combine(
    const float* __restrict__ x, float* __restrict__ out,
    const float* __restrict__ gamma, const float* __restrict__ beta, int b0)
{
    __shared__ float r1[8], r2[8];
    int b = blockIdx.y + b0, rp = blockIdx.x, t = threadIdx.x;
    int w = t >> 5, l = t & 31;
    int d4 = t << 2;
    const float* xb = x + (size_t)b * SS * DD;
    const float* ycs = g_ycs + (size_t)b * 2 * SH * DD;
    float4 gmv = ((const float4*)gamma)[t];
    float4 btv = ((const float4*)beta)[t];

    float4 vc, vs, va;
    if (rp < SH) {
        vc = *(const float4*)(ycs + (size_t)rp * DD + d4);
        vs = *(const float4*)(ycs + (size_t)(SH + rp) * DD + d4);
        float4 xv = *(const float4*)(xb + (size_t)rp * DD + d4);
        va = make_float4(vc.x + vs.x + 2.f * xv.x, vc.y + vs.y + 2.f * xv.y,
                         vc.z + vs.z + 2.f * xv.z, vc.w + vs.w + 2.f * xv.w);
    } else {
        // rp == 1024: ycos_1024[d] = sum_k (c/N)(-1)^f deltar[k][d]
        float a0 = 0.f, a1 = 0.f, a2 = 0.f, a3 = 0.f;
        const __nv_bfloat16* dr = g_delta + (size_t)b * K2 * DD;
        for (int k = 0; k < KK; k++) {
            int f = freq_of(k);
            float wgt = ((f == 0) ? 1.0f : 2.0f) * (1.0f / (float)NFFT);
            if (f & 1) wgt = -wgt;
            __nv_bfloat162 p0 = *(const __nv_bfloat162*)(dr + (size_t)k * DD + d4);
            __nv_bfloat162 p1 = *(const __nv_bfloat162*)(dr + (size_t)k * DD + d4 + 2);
            a0 += wgt * __bfloat162float(p0.x);
            a1 += wgt * __bfloat162float(p0.y);
            a2 += wgt * __bfloat162float(p1.x);
            a3 += wgt * __bfloat162float(p1.y);
        }
        float4 xv = *(const float4*)(xb + (size_t)SH * DD + d4);
        va = make_float4(a0 + 2.f * xv.x, a1 + 2.f * xv.y,
                         a2 + 2.f * xv.z, a3 + 2.f * xv.w);
    }

    // --- LN row A ---
    {
        float s1 = va.x + va.y + va.z + va.w;
        float s2 = va.x * va.x + va.y * va.y + va.z * va.z + va.w * va.w;
#pragma unroll
        for (int o = 16; o > 0; o >>= 1) {
            s1 += __shfl_down_sync(0xffffffffu, s1, o);
            s2 += __shfl_down_sync(0xffffffffu, s2, o);
        }
        if (l == 0) { r1[w] = s1; r2[w] = s2; }
        __syncthreads();
        float mu = 0.f, m2 = 0.f;
#pragma unroll
        for (int i = 0; i < 8; i++) { mu += r1[i]; m2 += r2[i]; }
        mu *= (1.0f / (float)DD);
        float var = m2 * (1.0f / (float)DD) - mu * mu;
        float rs = rsqrtf(var + 1e-5f);
        float* op = out + ((size_t)b * SS + rp) * DD + d4;
        op[0] = (va.x - mu) * rs * gmv.x + btv.x;
        op[1] = (va.y - mu) * rs * gmv.y + btv.y;
        op[2] = (va.z - mu) * rs * gmv.z + btv.z;
        op[3] = (va.w - mu) * rs * gmv.w + btv.w;
    }

    // --- row B: mirror 2048-rp, rp in 1..1023 ---
    if (rp >= 1 && rp < SH) {
        float4 xv = *(const float4*)(xb + (size_t)(SS - rp) * DD + d4);
        float4 vb = make_float4(vc.x - vs.x + 2.f * xv.x, vc.y - vs.y + 2.f * xv.y,
                                vc.z - vs.z + 2.f * xv.z, vc.w - vs.w + 2.f * xv.w);
        float s1 = vb.x + vb.y + vb.z + vb.w;
        float s2 = vb.x * vb.x + vb.y * vb.y + vb.z * vb.z + vb.w * vb.w;
#pragma unroll
        for (int o = 16; o > 0; o >>= 1) {
            s1 += __shfl_down_sync(0xffffffffu, s1, o);
            s2 += __shfl_down_sync(0xffffffffu, s2, o);
        }
        __syncthreads();   // protect r1/r2 reuse
        if (l == 0) { r1[w] = s1; r2[w] = s2; }
        __syncthreads();
        float mu = 0.f, m2 = 0.f;
#pragma unroll
        for (int i = 0; i < 8; i++) { mu += r1[i]; m2 += r2[i]; }
        mu *= (1.0f / (float)DD);
        float var = m2 * (1.0f / (float)DD) - mu * mu;
        float rs = rsqrtf(var + 1e-5f);
        float* op = out + ((size_t)b * SS + (SS - rp)) * DD + d4;
        op[0] = (vb.x - mu) * rs * gmv.x + btv.x;
        op[1] = (vb.y - mu) * rs * gmv.y + btv.y;
        op[2] = (vb.z - mu) * rs * gmv.z + btv.z;
        op[3] = (vb.w - mu) * rs * gmv.w + btv.w;
    }
}

// ---------------- launch ----------------
extern "C" void kernel_launch(void* const* d_in, const int* in_sizes, int n_in,
                              void* d_out, int out_size) {
    const float* x     = (const float*)d_in[0];
    const float* mag   = (const float*)d_in[1];
    const float* ph    = (const float*)d_in[2];
    const float* W     = (const float*)d_in[3];
    const float* gamma = (const float*)d_in[4];
    const float* beta  = (const float*)d_in[5];
    float* out = (float*)d_out;

    void *p_b1, *p_b2, *p_wt, *p_xc, *p_xd, *p_X, *p_xwr, *p_dp, *p_dl, *p_ycs;
    cudaGetSymbolAddress(&p_b1, g_basis1f);
    cudaGetSymbolAddress(&p_b2, g_basis2f);
    cudaGetSymbolAddress(&p_wt, g_wt);
    cudaGetSymbolAddress(&p_xc, g_xc);
    cudaGetSymbolAddress(&p_xd, g_xd);
    cudaGetSymbolAddress(&p_X, g_X);
    cudaGetSymbolAddress(&p_xwr, g_xwr);
    cudaGetSymbolAddress(&p_dp, g_dpart);
    cudaGetSymbolAddress(&p_dl, g_delta);
    cudaGetSymbolAddress(&p_ycs, g_ycs);

    cudaFuncSetAttribute(gemm_mma<1>, cudaFuncAttributeMaxDynamicSharedMemorySize, GEMM_SMEM);
    cudaFuncSetAttribute(gemm_mma<3>, cudaFuncAttributeMaxDynamicSharedMemorySize, GEMM_SMEM);

    // one-time resource setup (runs during the uncaptured correctness call;
    // identical GPU work is issued on every call)
    static cudaStream_t sPre = [] { cudaStream_t s; cudaStreamCreateWithFlags(&s, cudaStreamNonBlocking); return s; }();
    static cudaStream_t sB   = [] { cudaStream_t s; cudaStreamCreateWithFlags(&s, cudaStreamNonBlocking); return s; }();
    static cudaEvent_t eFork = [] { cudaEvent_t e; cudaEventCreateWithFlags(&e, cudaEventDisableTiming); return e; }();
    static cudaEvent_t ePre  = [] { cudaEvent_t e; cudaEventCreateWithFlags(&e, cudaEventDisableTiming); return e; }();
    static cudaEvent_t eMid  = [] { cudaEvent_t e; cudaEventCreateWithFlags(&e, cudaEventDisableTiming); return e; }();
    static cudaEvent_t eBend = [] { cudaEvent_t e; cudaEventCreateWithFlags(&e, cudaEventDisableTiming); return e; }();

    cudaStream_t s0 = 0;   // default (capture) stream — chain A lives here

    // ---- fork: precompute on sPre, fold on s0, concurrently ----
    cudaEventRecord(eFork, s0);
    cudaStreamWaitEvent(sPre, eFork, 0);
    k_tbl<<<NFFT / 256, 256, 0, sPre>>>();
    k_pre<<<(N_CW + 255) / 256, 256, 0, sPre>>>(W, mag, ph);
    cudaEventRecord(ePre, sPre);

    k_fold<<<(BB * SH * (DD / 4)) / 256, 256, 0, s0>>>(x);

    // join precompute; then fork chain B
    cudaStreamWaitEvent(s0, ePre, 0);
    cudaEventRecord(eMid, s0);
    cudaStreamWaitEvent(sB, eMid, 0);

    // ---- two independent per-batch-half chains ----
    struct { cudaStream_t st; int b0; } chains[2] = { { s0, 0 }, { sB, HB } };
    for (int c = 0; c < 2; c++) {
        cudaStream_t st = chains[c].st;
        int b0 = chains[c].b0;

        // G1 (folded): X[b] = basis1f @ {xc|xd}[b], +x0 on cos tiles
        gemm_mma<3><<<dim3(DD / BN, K2 / BM, HB), 256, GEMM_SMEM, st>>>(
            (const __nv_bfloat16*)p_b1, SH,
            (const __nv_bfloat16*)p_xc, (const __nv_bfloat16*)p_xd, (size_t)SH * DD, DD,
            p_X, (size_t)K2 * DD, DD,
            x, (size_t)SS * DD,
            SH, /*bsel=*/2, b0);

        // elementwise complex weighting
        k_elem<<<(HB * KK * DD) / 256, 256, 0, st>>>(b0);

        // interference: deltar[b] = dpart + 0.1 * (WT @ xwr[b])
        gemm_mma<1><<<dim3(DD / BN, KK / BM, HB), 256, GEMM_SMEM, st>>>(
            (const __nv_bfloat16*)p_wt, KK,
            (const __nv_bfloat16*)p_xwr, (const __nv_bfloat16*)p_xwr, (size_t)KK * DD, DD,
            p_dl, (size_t)K2 * DD, DD,
            (const float*)p_dp, (size_t)KK * DD,
            KK, /*bsel=*/8, b0);

        // G2 (folded): ycs[b] = basis2f @ {deltar|deltai}[b]
        gemm_mma<3><<<dim3(DD / BN, (2 * SH) / BM, HB), 256, GEMM_SMEM, st>>>(
            (const __nv_bfloat16*)p_b2, KK,
            (const __nv_bfloat16*)p_dl, (const __nv_bfloat16*)p_dl + (size_t)KK * DD,
            (size_t)K2 * DD, DD,
            p_ycs, (size_t)2 * SH * DD, DD,
            nullptr, 0,
            KK, /*bsel=*/8, b0);

        // combine: mirror + residual + row1024 + LayerNorm
        k_combine<<<dim3(SH + 1, HB), 256, 0, st>>>(x, out, gamma, beta, b0);
    }

    // ---- join chain B back into the capture stream ----
    cudaEventRecord(eBend, sB);
    cudaStreamWaitEvent(s0, eBend, 0);
}